// round 1
// baseline (speedup 1.0000x reference)
#include <cuda_runtime.h>

#define DD 48
#define HH 160
#define WW 160
#define HWW (HH*WW)
#define DHW (DD*HH*WW)
#define NID 15
#define NBIN 8192
#define NPAIR 30

// ---------------- static device scratch (no allocations allowed) ----------------
__device__ double   g_stats[2][16][10];        // [b][id][cnt,Sx,Sy,Sz,Ss0..2,Sq0..2]
__device__ unsigned g_hist[NPAIR * 2 * NBIN];  // [pair][fg/bg][bin] counts
__device__ double   g_seed_bg[2];
__device__ double   g_seed_fg[2];
__device__ double   g_lov[NPAIR];
__device__ double   g_var[NPAIR];
__device__ double   g_cntd[NPAIR];
__device__ int      g_present[NPAIR];
__device__ float    g_params[NPAIR][6];        // cx,cy,cz,s0,s1,s2

__device__ __forceinline__ float sigmoidf_(float x) {
    return 1.0f / (1.0f + __expf(-x));
}

// ---------------- K1: per-id stats + seed_bg ----------------
__global__ void k1_stats(const float* __restrict__ pred,
                         const int* __restrict__ inst,
                         const int* __restrict__ lab) {
    __shared__ float sh[16][10];
    int t = threadIdx.x;
    int b = blockIdx.y;
    for (int i = t; i < 160; i += 256) ((float*)sh)[i] = 0.f;
    __syncthreads();

    const float* pb = pred + (size_t)b * 7 * DHW;
    double sbg = 0.0;

    for (int r = blockIdx.x * 256 + t; r < DHW; r += gridDim.x * 256) {
        int id = inst[b * DHW + r];
        float p6 = pb[6 * DHW + r];
        float sd = sigmoidf_(p6);
        if (lab[b * DHW + r] == 0) sbg += (double)(sd * sd);
        if (id > 0) {
            int x = r % WW;
            int tmp = r / WW;
            int y = tmp % HH;
            int z = tmp / HH;
            float s0 = pb[3 * DHW + r];
            float s1 = pb[4 * DHW + r];
            float s2 = pb[5 * DHW + r];
            float* row = sh[id];
            atomicAdd(row + 0, 1.0f);
            atomicAdd(row + 1, (float)x);
            atomicAdd(row + 2, (float)y);
            atomicAdd(row + 3, (float)z);
            atomicAdd(row + 4, s0);
            atomicAdd(row + 5, s1);
            atomicAdd(row + 6, s2);
            atomicAdd(row + 7, s0 * s0);
            atomicAdd(row + 8, s1 * s1);
            atomicAdd(row + 9, s2 * s2);
        }
    }

    // seed_bg: warp reduce then one double atomic per warp
    for (int o = 16; o > 0; o >>= 1) sbg += __shfl_down_sync(0xffffffffu, sbg, o);
    if ((t & 31) == 0) atomicAdd(&g_seed_bg[b], sbg);

    __syncthreads();
    if (t < 150) {
        int id = 1 + t / 10, col = t % 10;
        float v = sh[id][col];
        if (v != 0.f) atomicAdd(&g_stats[b][id][col], (double)v);
    }
}

// ---------------- K2: centers / s / var per (b,id) ----------------
__global__ void k2_params() {
    int t = threadIdx.x;
    if (t >= NPAIR) return;
    int b = t / NID, i = t % NID;
    double* st = g_stats[b][i + 1];
    double cnt = st[0];
    int pres = (cnt > 0.0) ? 1 : 0;
    double c = (cnt > 0.0) ? cnt : 1.0;
    double cx = st[1] / (159.0 * c);
    double cy = st[2] / (159.0 * c);
    double cz = st[3] / (47.0 * c);
    double m0 = st[4] / c, m1 = st[5] / c, m2 = st[6] / c;
    double var = 0.0;
    if (pres) {
        var = (st[7] / c - m0 * m0) + (st[8] / c - m1 * m1) + (st[9] / c - m2 * m2);
    }
    g_var[t] = var;
    g_present[t] = pres;
    g_cntd[t] = cnt;
    g_params[t][0] = (float)cx;
    g_params[t][1] = (float)cy;
    g_params[t][2] = (float)cz;
    g_params[t][3] = expf(fminf((float)(10.0 * m0), 80.f));
    g_params[t][4] = expf(fminf((float)(10.0 * m1), 80.f));
    g_params[t][5] = expf(fminf((float)(10.0 * m2), 80.f));
}

// ---------------- K3: main per-pixel kernel — histograms + seed_fg ----------------
__global__ void k3_main(const float* __restrict__ pred,
                        const int* __restrict__ inst) {
    __shared__ float prm[NID][6];
    __shared__ int spres[NID];
    int t = threadIdx.x, b = blockIdx.y;
    if (t < NID * 6) ((float*)prm)[t] = ((const float*)g_params)[b * NID * 6 + t];
    if (t < NID) spres[t] = g_present[b * NID + t];
    __syncthreads();

    int r = blockIdx.x * 256 + t;  // grid.x*256 == DHW exactly
    const float* pb = pred + (size_t)b * 7 * DHW + r;
    float p0 = pb[0];
    float p1 = pb[DHW];
    float p2 = pb[2 * DHW];
    float p6 = pb[6 * DHW];
    int x = r % WW;
    int tmp = r / WW;
    int y = tmp % HH;
    int z = tmp / HH;
    float e0 = tanhf(p0) + (float)x * (1.0f / 159.0f);
    float e1 = tanhf(p1) + (float)y * (1.0f / 159.0f);
    float e2 = tanhf(p2) + (float)z * (1.0f / 47.0f);
    float seed = sigmoidf_(p6);
    int own = inst[b * DHW + r];
    float sfg = 0.f;
    unsigned* hbase = g_hist + (size_t)b * NID * 2 * NBIN;

#pragma unroll 1
    for (int i = 0; i < NID; i++) {
        if (!spres[i]) continue;
        float dx = e0 - prm[i][0];
        float dy = e1 - prm[i][1];
        float dz = e2 - prm[i][2];
        float d2 = dx * dx * prm[i][3] + dy * dy * prm[i][4] + dz * dz * prm[i][5];
        float dist = __expf(-d2);
        bool isfg = (own == i + 1);
        float e = isfg ? (2.0f - 2.0f * dist) : (2.0f * dist);
        int bin = (int)(e * (float)(NBIN / 2));
        bin = bin < 0 ? 0 : (bin > NBIN - 1 ? NBIN - 1 : bin);
        atomicAdd(hbase + ((size_t)i * 2 + (isfg ? 0 : 1)) * NBIN + bin, 1u);
        if (isfg) {
            float dd = seed - dist;
            sfg += dd * dd;
        }
    }
    for (int o = 16; o > 0; o >>= 1) sfg += __shfl_down_sync(0xffffffffu, sfg, o);
    if ((t & 31) == 0) atomicAdd(&g_seed_fg[b], (double)sfg);
}

// ---------------- K4: Lovász from histograms (descending-e scan) ----------------
__global__ void k4_lovasz() {
    int pair = blockIdx.x;
    int t = threadIdx.x;
    if (!g_present[pair]) {
        if (t == 0) g_lov[pair] = 0.0;
        return;
    }
    __shared__ unsigned sF[256], sB[256];
    __shared__ double sred[256];

    double G = g_cntd[pair];
    const unsigned* hf = g_hist + (size_t)pair * 2 * NBIN;
    const unsigned* hb = hf + NBIN;

    unsigned f[32], bc[32];
    unsigned tf = 0, tb = 0;
    int base = t * 32;
#pragma unroll
    for (int k = 0; k < 32; k++) {
        int bin = NBIN - 1 - (base + k);
        f[k] = hf[bin];
        bc[k] = hb[bin];
        tf += f[k];
        tb += bc[k];
    }
    sF[t] = tf;
    sB[t] = tb;
    __syncthreads();

    // inclusive Hillis-Steele scan over 256 per-thread totals
    for (int off = 1; off < 256; off <<= 1) {
        unsigned aF = 0, aB = 0;
        if (t >= off) { aF = sF[t - off]; aB = sB[t - off]; }
        __syncthreads();
        sF[t] += aF;
        sB[t] += aB;
        __syncthreads();
    }
    unsigned F = sF[t] - tf;  // exclusive fg before my range
    unsigned Q = sB[t] - tb;  // exclusive bg before my range

    double acc = 0.0;
#pragma unroll
    for (int k = 0; k < 32; k++) {
        unsigned fk = f[k], bk = bc[k];
        if (fk | bk) {
            int bin = NBIN - 1 - (base + k);
            double e = ((double)bin + 0.5) * (2.0 / (double)NBIN);
            double GQ = G + (double)Q;
            if (fk) acc += e * (double)fk / (GQ + 0.5 * (double)bk);
            if (bk) acc += e * (G - (double)F - 0.5 * (double)fk) *
                           (1.0 / GQ - 1.0 / (GQ + (double)bk));
            F += fk;
            Q += bk;
        }
    }
    sred[t] = acc;
    __syncthreads();
    for (int s = 128; s > 0; s >>= 1) {
        if (t < s) sred[t] += sred[t + s];
        __syncthreads();
    }
    if (t == 0) g_lov[pair] = sred[0];
}

// ---------------- K5: combine to scalar ----------------
__global__ void k5_final(float* out) {
    double total = 0.0;
    for (int b = 0; b < 2; b++) {
        double pres = 0, lov = 0, var = 0;
        for (int i = 0; i < NID; i++) {
            int p = b * NID + i;
            pres += (double)g_present[p];
            lov += g_lov[p];
            var += g_var[p];
        }
        double denom = pres > 1.0 ? pres : 1.0;
        double L = lov / denom + 10.0 * (var / denom) +
                   (g_seed_bg[b] + g_seed_fg[b]) / (double)DHW;
        total += L;
    }
    out[0] = (float)(0.5 * total);
}

// ---------------- launch ----------------
extern "C" void kernel_launch(void* const* d_in, const int* in_sizes, int n_in,
                              void* d_out, int out_size) {
    const float* pred = (const float*)d_in[0];
    const int* inst = (const int*)d_in[1];
    const int* lab = (const int*)d_in[2];
    // d_in[3] = center_images (unused by the reference loss)

    void* p;
    cudaGetSymbolAddress(&p, g_stats);
    cudaMemsetAsync(p, 0, sizeof(double) * 2 * 16 * 10);
    cudaGetSymbolAddress(&p, g_hist);
    cudaMemsetAsync(p, 0, sizeof(unsigned) * NPAIR * 2 * NBIN);
    cudaGetSymbolAddress(&p, g_seed_bg);
    cudaMemsetAsync(p, 0, sizeof(double) * 2);
    cudaGetSymbolAddress(&p, g_seed_fg);
    cudaMemsetAsync(p, 0, sizeof(double) * 2);

    k1_stats<<<dim3(1200, 2), 256>>>(pred, inst, lab);
    k2_params<<<1, 32>>>();
    k3_main<<<dim3(DHW / 256, 2), 256>>>(pred, inst);
    k4_lovasz<<<NPAIR, 256>>>();
    k5_final<<<1, 1>>>((float*)d_out);
}